// round 13
// baseline (speedup 1.0000x reference)
#include <cuda_runtime.h>

#define BB 4
#define HH 16
#define SS 4096
#define DD 64
#define NBH (BB*HH)
#define NCHUNK 8
#define EPS 1e-6f

__device__ float g_kv[NBH * DD * DD];             // [bh][d][f] (final)
__device__ float g_kvp[NCHUNK * NBH * DD * DD];   // per-chunk partials (8MB)
__device__ float g_ksum[NBH * DD];                // [bh][d]
__device__ int   g_mask_fmt;                      // 0 = 4-byte elems, 1 = 1-byte

typedef unsigned long long ull;

// ---------- helpers ----------
__device__ __forceinline__ float fmap(float x) {
    return x > 0.0f ? x + 1.0f : __expf(x);
}

__device__ __forceinline__ void fma2(ull &acc, ull a, ull b) {
    asm("fma.rn.f32x2 %0, %1, %2, %0;" : "+l"(acc) : "l"(a), "l"(b));
}

__device__ __forceinline__ ull packf2(float x, float y) {
    ull r;
    asm("mov.b64 %0, {%1, %2};" : "=l"(r) : "f"(x), "f"(y));
    return r;
}

__device__ __forceinline__ float2 unpackf2(ull v) {
    float2 r;
    asm("mov.b64 {%0, %1}, %2;" : "=f"(r.x), "=f"(r.y) : "l"(v));
    return r;
}

__device__ __forceinline__ float get_valid(const void* mask, int fmt, int idx) {
    if (fmt) return ((const unsigned char*)mask)[idx] == 0 ? 1.0f : 0.0f;
    return ((const unsigned int*)mask)[idx] == 0u ? 1.0f : 0.0f;
}

// ---------- small kernels ----------
__global__ void zero_kernel() {
    int idx = blockIdx.x * blockDim.x + threadIdx.x;
    if (idx < NBH * DD) g_ksum[idx] = 0.0f;
    if (idx == 0)       g_mask_fmt = 0;
}

__global__ void detect_kernel(const unsigned int* __restrict__ mask) {
    int idx = blockIdx.x * blockDim.x + threadIdx.x;  // 4096 threads
    unsigned int w = mask[idx];
    if (w != 0u && w != 1u && w != 0x3F800000u) atomicOr(&g_mask_fmt, 1);
}

// Sum the NCHUNK partial kv matrices. grid 512 x 128 threads, 1 float4/thread.
__global__ void __launch_bounds__(128)
reduce_kernel() {
    const int gidx = blockIdx.x * 128 + threadIdx.x;   // 0..65535
    const int bh  = gidx >> 10;
    const int pos = gidx & 1023;
    const float4* src = (const float4*)g_kvp;
    float4 s = src[(size_t)bh * 1024 + pos];
#pragma unroll
    for (int c = 1; c < NCHUNK; c++) {
        float4 t = src[(size_t)(c * NBH + bh) * 1024 + pos];
        s.x += t.x; s.y += t.y; s.z += t.z; s.w += t.w;
    }
    ((float4*)(g_kv + bh * DD * DD))[pos] = s;
}

// ---------- Pass 1 ----------
// grid (NCHUNK, 64), 128 threads. Thread (i=tid&15, j=tid>>4) owns the
// DISJOINT tile d=4i..4i+3 x f=8j..8j+7 (16 FMA2/token). 16-token stages,
// double-buffered register prefetch, loader-side ksum.
__global__ void __launch_bounds__(128)
pass1_kernel(const float* __restrict__ kk, const float* __restrict__ vv,
             const void* __restrict__ mask) {
    __shared__ float ksh[2][1024];        // 16 tokens x 64
    __shared__ float vsh[2][1024];
    __shared__ float ksbuf[4 * 16 * 4];   // per-warp ksum partials

    const int bh  = blockIdx.y;
    const int s0  = blockIdx.x * 512;
    const int tid = threadIdx.x;
    const int i   = tid & 15;        // d group: d = 4i..4i+3
    const int j   = tid >> 4;        // f group: f = 8j..8j+7
    const int fmt = g_mask_fmt;
    const int b   = bh >> 4;

    const float4* kg = (const float4*)(kk + (size_t)bh * SS * DD);
    const float4* vg = (const float4*)(vv + (size_t)bh * SS * DD);

    ull acc[4][4];
#pragma unroll
    for (int a = 0; a < 4; a++)
#pragma unroll
        for (int p = 0; p < 4; p++) acc[a][p] = 0ull;
    // loader-side ksum for k-cols 4*(tid&15)..+3 (c4 == i on all loads)
    float4 ks4 = make_float4(0.f, 0.f, 0.f, 0.f);

    float4 kr[2], vr[2];

    // prefetch stage 0 (16 tokens = 256 float4, 2 per thread)
#pragma unroll
    for (int it = 0; it < 2; it++) {
        int vi = it * 128 + tid;
        int sl = vi >> 4, c4 = vi & 15;
        float valid = get_valid(mask, fmt, b * SS + s0 + sl);
        float4 k4 = kg[(size_t)(s0 + sl) * 16 + c4];
        vr[it] = vg[(size_t)(s0 + sl) * 16 + c4];
        k4.x = fmap(k4.x) * valid;
        k4.y = fmap(k4.y) * valid;
        k4.z = fmap(k4.z) * valid;
        k4.w = fmap(k4.w) * valid;
        kr[it] = k4;
        ks4.x += k4.x; ks4.y += k4.y; ks4.z += k4.z; ks4.w += k4.w;
    }

    for (int st = 0; st < 32; st++) {
        const int bufi = st & 1;
        // store current stage regs -> smem
#pragma unroll
        for (int it = 0; it < 2; it++) {
            ((float4*)ksh[bufi])[it * 128 + tid] = kr[it];
            ((float4*)vsh[bufi])[it * 128 + tid] = vr[it];
        }
        __syncthreads();

        // prefetch next stage (overlaps with compute below)
        if (st < 31) {
            const int sbase = s0 + (st + 1) * 16;
#pragma unroll
            for (int it = 0; it < 2; it++) {
                int vi = it * 128 + tid;
                int sl = vi >> 4, c4 = vi & 15;
                float valid = get_valid(mask, fmt, b * SS + sbase + sl);
                float4 k4 = kg[(size_t)(sbase + sl) * 16 + c4];
                vr[it] = vg[(size_t)(sbase + sl) * 16 + c4];
                k4.x = fmap(k4.x) * valid;
                k4.y = fmap(k4.y) * valid;
                k4.z = fmap(k4.z) * valid;
                k4.w = fmap(k4.w) * valid;
                kr[it] = k4;
                ks4.x += k4.x; ks4.y += k4.y; ks4.z += k4.z; ks4.w += k4.w;
            }
        }

        // compute 16 tokens: 3 LDS.128 + 4 packs + 16 FMA2 per token
        const float* kb = ksh[bufi];
        const float* vb = vsh[bufi];
#pragma unroll 8
        for (int m = 0; m < 16; m++) {
            float4 kd = *(const float4*)(kb + m * 64 + 4 * i);
            ulonglong2 va = *(const ulonglong2*)(vb + m * 64 + 8 * j);
            ulonglong2 vc = *(const ulonglong2*)(vb + m * 64 + 8 * j + 4);
            ull p;
            p = packf2(kd.x, kd.x);
            fma2(acc[0][0], p, va.x); fma2(acc[0][1], p, va.y);
            fma2(acc[0][2], p, vc.x); fma2(acc[0][3], p, vc.y);
            p = packf2(kd.y, kd.y);
            fma2(acc[1][0], p, va.x); fma2(acc[1][1], p, va.y);
            fma2(acc[1][2], p, vc.x); fma2(acc[1][3], p, vc.y);
            p = packf2(kd.z, kd.z);
            fma2(acc[2][0], p, va.x); fma2(acc[2][1], p, va.y);
            fma2(acc[2][2], p, vc.x); fma2(acc[2][3], p, vc.y);
            p = packf2(kd.w, kd.w);
            fma2(acc[3][0], p, va.x); fma2(acc[3][1], p, va.y);
            fma2(acc[3][2], p, vc.x); fma2(acc[3][3], p, vc.y);
        }
        // no trailing sync: next iteration's barrier protects the other buffer
    }

    // store this block's partial kv tile (disjoint per thread — plain stores)
    float* dst = g_kvp + (size_t)(blockIdx.x * NBH + bh) * DD * DD;
#pragma unroll
    for (int a = 0; a < 4; a++) {
        float2 u0 = unpackf2(acc[a][0]);
        float2 u1 = unpackf2(acc[a][1]);
        float2 u2 = unpackf2(acc[a][2]);
        float2 u3 = unpackf2(acc[a][3]);
        float* row = dst + (4 * i + a) * 64 + 8 * j;
        *(float4*)(row)     = make_float4(u0.x, u0.y, u1.x, u1.y);
        *(float4*)(row + 4) = make_float4(u2.x, u2.y, u3.x, u3.y);
    }

    // ksum reduce: lanes l and l^16 hold the same c4 column group
    ks4.x += __shfl_xor_sync(0xffffffffu, ks4.x, 16);
    ks4.y += __shfl_xor_sync(0xffffffffu, ks4.y, 16);
    ks4.z += __shfl_xor_sync(0xffffffffu, ks4.z, 16);
    ks4.w += __shfl_xor_sync(0xffffffffu, ks4.w, 16);
    const int lane = tid & 31, w = tid >> 5;
    __syncthreads();     // done with ksh/vsh reads
    if (lane < 16)
        *(float4*)(ksbuf + (w * 16 + lane) * 4) = ks4;
    __syncthreads();
    if (tid < 64) {
        const int c4 = tid & 15, comp = tid >> 4;
        float s = 0.f;
#pragma unroll
        for (int ww = 0; ww < 4; ww++)
            s += ksbuf[(ww * 16 + c4) * 4 + comp];
        atomicAdd(&g_ksum[bh * DD + 4 * c4 + comp], s);
    }
}

// ---------- Pass 2 ---------- (R11 winner, verbatim)
// grid (32, 64), 128 threads, 128 tokens/block, thread tile 8t x 8f.
__global__ void __launch_bounds__(128)
pass2_kernel(const float* __restrict__ qq, float* __restrict__ out) {
    __shared__ float qsh[64 * 128];   // [d][t]
    __shared__ float kvsh[64 * 64];   // [d][f]
    __shared__ float kss[64];
    __shared__ float zsh[128];

    const int bh  = blockIdx.y;
    const int t0  = blockIdx.x * 128;
    const int tid = threadIdx.x;

    const float4* kvg = (const float4*)(g_kv + bh * DD * DD);
#pragma unroll
    for (int it = 0; it < 8; it++)
        ((float4*)kvsh)[it * 128 + tid] = kvg[it * 128 + tid];
    if (tid < 16)
        ((float4*)kss)[tid] = ((const float4*)(g_ksum + bh * DD))[tid];

    const float4* qg = (const float4*)(qq + (size_t)bh * SS * DD + (size_t)t0 * DD);
    float4 qr[16];
#pragma unroll
    for (int c = 0; c < 16; c++) {
        float4 x = qg[tid * 16 + c];
        x.x = fmap(x.x); x.y = fmap(x.y); x.z = fmap(x.z); x.w = fmap(x.w);
        qr[c] = x;
    }
    __syncthreads();

    float z = EPS;
#pragma unroll
    for (int c = 0; c < 16; c++) {
        z += qr[c].x * kss[4 * c] + qr[c].y * kss[4 * c + 1]
           + qr[c].z * kss[4 * c + 2] + qr[c].w * kss[4 * c + 3];
    }
    zsh[tid] = 1.0f / z;

#pragma unroll
    for (int c = 0; c < 16; c++) {
        qsh[(4 * c + 0) * 128 + tid] = qr[c].x;
        qsh[(4 * c + 1) * 128 + tid] = qr[c].y;
        qsh[(4 * c + 2) * 128 + tid] = qr[c].z;
        qsh[(4 * c + 3) * 128 + tid] = qr[c].w;
    }
    __syncthreads();

    const int ty = tid >> 3;   // 0..15
    const int tx = tid & 7;    // 0..7

    ull acc[8][4];
#pragma unroll
    for (int r = 0; r < 8; r++)
#pragma unroll
        for (int p = 0; p < 4; p++) acc[r][p] = 0ull;

#pragma unroll 4
    for (int d = 0; d < 64; d++) {
        float4 qa = *(const float4*)(qsh + d * 128 + 4 * ty);
        float4 qb = *(const float4*)(qsh + d * 128 + 64 + 4 * ty);
        ulonglong2 va = *(const ulonglong2*)(kvsh + d * 64 + 4 * tx);
        ulonglong2 vb = *(const ulonglong2*)(kvsh + d * 64 + 32 + 4 * tx);
        float qs[8] = {qa.x, qa.y, qa.z, qa.w, qb.x, qb.y, qb.z, qb.w};
#pragma unroll
        for (int r = 0; r < 8; r++) {
            ull qp = packf2(qs[r], qs[r]);
            fma2(acc[r][0], qp, va.x);
            fma2(acc[r][1], qp, va.y);
            fma2(acc[r][2], qp, vb.x);
            fma2(acc[r][3], qp, vb.y);
        }
    }

#pragma unroll
    for (int r = 0; r < 8; r++) {
        const int t = (r < 4) ? (4 * ty + r) : (64 + 4 * ty + r - 4);
        const float invz = zsh[t];
        float* og = out + (size_t)bh * SS * DD + (size_t)(t0 + t) * DD;
        float2 a0 = unpackf2(acc[r][0]);
        float2 a1 = unpackf2(acc[r][1]);
        float2 a2 = unpackf2(acc[r][2]);
        float2 a3 = unpackf2(acc[r][3]);
        float4 o0 = make_float4(a0.x * invz, a0.y * invz, a1.x * invz, a1.y * invz);
        float4 o1 = make_float4(a2.x * invz, a2.y * invz, a3.x * invz, a3.y * invz);
        *(float4*)(og + 4 * tx)      = o0;
        *(float4*)(og + 32 + 4 * tx) = o1;
    }
}

extern "C" void kernel_launch(void* const* d_in, const int* in_sizes, int n_in,
                              void* d_out, int out_size) {
    const float* q = (const float*)d_in[0];
    const float* k = (const float*)d_in[1];
    const float* v = (const float*)d_in[2];
    const void*  m = d_in[3];
    float* out = (float*)d_out;

    zero_kernel<<<16, 256>>>();
    detect_kernel<<<16, 256>>>((const unsigned int*)m);
    pass1_kernel<<<dim3(NCHUNK, NBH), 128>>>(k, v, m);
    reduce_kernel<<<512, 128>>>();
    pass2_kernel<<<dim3(SS / 128, NBH), 128>>>(q, out);
}

// round 14
// speedup vs baseline: 1.1039x; 1.1039x over previous
#include <cuda_runtime.h>

#define BB 4
#define HH 16
#define SS 4096
#define DD 64
#define NBH (BB*HH)
#define NCHUNK 16
#define EPS 1e-6f

__device__ float g_kv[NBH * DD * DD];             // [bh][d][f] (final)
__device__ float g_kvp[NCHUNK * NBH * DD * DD];   // per-chunk partials (16MB)
__device__ float g_ksum[NBH * DD];                // [bh][d]
__device__ int   g_mask_fmt;                      // 0 = 4-byte elems, 1 = 1-byte

typedef unsigned long long ull;

// ---------- helpers ----------
__device__ __forceinline__ float fmap(float x) {
    return x > 0.0f ? x + 1.0f : __expf(x);
}

__device__ __forceinline__ void fma2(ull &acc, ull a, ull b) {
    asm("fma.rn.f32x2 %0, %1, %2, %0;" : "+l"(acc) : "l"(a), "l"(b));
}

__device__ __forceinline__ ull packf2(float x, float y) {
    ull r;
    asm("mov.b64 %0, {%1, %2};" : "=l"(r) : "f"(x), "f"(y));
    return r;
}

__device__ __forceinline__ float2 unpackf2(ull v) {
    float2 r;
    asm("mov.b64 {%0, %1}, %2;" : "=f"(r.x), "=f"(r.y) : "l"(v));
    return r;
}

__device__ __forceinline__ float get_valid(const void* mask, int fmt, int idx) {
    if (fmt) return ((const unsigned char*)mask)[idx] == 0 ? 1.0f : 0.0f;
    return ((const unsigned int*)mask)[idx] == 0u ? 1.0f : 0.0f;
}

// ---------- small kernels ----------
__global__ void zero_kernel() {
    int idx = blockIdx.x * blockDim.x + threadIdx.x;
    if (idx < NBH * DD) g_ksum[idx] = 0.0f;
    if (idx == 0)       g_mask_fmt = 0;
}

__global__ void detect_kernel(const unsigned int* __restrict__ mask) {
    int idx = blockIdx.x * blockDim.x + threadIdx.x;  // 4096 threads
    unsigned int w = mask[idx];
    if (w != 0u && w != 1u && w != 0x3F800000u) atomicOr(&g_mask_fmt, 1);
}

// Sum the NCHUNK partial kv matrices. grid 512 x 128 threads, 1 float4/thread.
__global__ void __launch_bounds__(128)
reduce_kernel() {
    const int gidx = blockIdx.x * 128 + threadIdx.x;   // 0..65535
    const int bh  = gidx >> 10;
    const int pos = gidx & 1023;
    const float4* src = (const float4*)g_kvp;
    float4 s = src[(size_t)bh * 1024 + pos];
#pragma unroll
    for (int c = 1; c < NCHUNK; c++) {
        float4 t = src[(size_t)(c * NBH + bh) * 1024 + pos];
        s.x += t.x; s.y += t.y; s.z += t.z; s.w += t.w;
    }
    ((float4*)(g_kv + bh * DD * DD))[pos] = s;
}

// ---------- Pass 1 ----------
// grid (NCHUNK, 64) = 1024 blocks, 128 threads. Thread (i=tid&15, j=tid>>4)
// owns the DISJOINT tile d=4i..4i+3 x f=8j..8j+7. 256 tokens/block,
// 16-token double-buffered stages, loader-side ksum.
__global__ void __launch_bounds__(128)
pass1_kernel(const float* __restrict__ kk, const float* __restrict__ vv,
             const void* __restrict__ mask) {
    __shared__ float ksh[2][1024];        // 16 tokens x 64
    __shared__ float vsh[2][1024];
    __shared__ float ksbuf[4 * 16 * 4];   // per-warp ksum partials

    const int bh  = blockIdx.y;
    const int s0  = blockIdx.x * 256;
    const int tid = threadIdx.x;
    const int i   = tid & 15;        // d group: d = 4i..4i+3
    const int j   = tid >> 4;        // f group: f = 8j..8j+7
    const int fmt = g_mask_fmt;
    const int b   = bh >> 4;

    const float4* kg = (const float4*)(kk + (size_t)bh * SS * DD);
    const float4* vg = (const float4*)(vv + (size_t)bh * SS * DD);

    ull acc[4][4];
#pragma unroll
    for (int a = 0; a < 4; a++)
#pragma unroll
        for (int p = 0; p < 4; p++) acc[a][p] = 0ull;
    float4 ks4 = make_float4(0.f, 0.f, 0.f, 0.f);

    float4 kr[2], vr[2];

    // prefetch stage 0 (16 tokens = 256 float4, 2 per thread)
#pragma unroll
    for (int it = 0; it < 2; it++) {
        int vi = it * 128 + tid;
        int sl = vi >> 4, c4 = vi & 15;
        float valid = get_valid(mask, fmt, b * SS + s0 + sl);
        float4 k4 = kg[(size_t)(s0 + sl) * 16 + c4];
        vr[it] = vg[(size_t)(s0 + sl) * 16 + c4];
        k4.x = fmap(k4.x) * valid;
        k4.y = fmap(k4.y) * valid;
        k4.z = fmap(k4.z) * valid;
        k4.w = fmap(k4.w) * valid;
        kr[it] = k4;
        ks4.x += k4.x; ks4.y += k4.y; ks4.z += k4.z; ks4.w += k4.w;
    }

    for (int st = 0; st < 16; st++) {
        const int bufi = st & 1;
#pragma unroll
        for (int it = 0; it < 2; it++) {
            ((float4*)ksh[bufi])[it * 128 + tid] = kr[it];
            ((float4*)vsh[bufi])[it * 128 + tid] = vr[it];
        }
        __syncthreads();

        // prefetch next stage (overlaps with compute below)
        if (st < 15) {
            const int sbase = s0 + (st + 1) * 16;
#pragma unroll
            for (int it = 0; it < 2; it++) {
                int vi = it * 128 + tid;
                int sl = vi >> 4, c4 = vi & 15;
                float valid = get_valid(mask, fmt, b * SS + sbase + sl);
                float4 k4 = kg[(size_t)(sbase + sl) * 16 + c4];
                vr[it] = vg[(size_t)(sbase + sl) * 16 + c4];
                k4.x = fmap(k4.x) * valid;
                k4.y = fmap(k4.y) * valid;
                k4.z = fmap(k4.z) * valid;
                k4.w = fmap(k4.w) * valid;
                kr[it] = k4;
                ks4.x += k4.x; ks4.y += k4.y; ks4.z += k4.z; ks4.w += k4.w;
            }
        }

        // compute 16 tokens: 3 LDS.128 + 4 packs + 16 FMA2 per token
        const float* kb = ksh[bufi];
        const float* vb = vsh[bufi];
#pragma unroll 8
        for (int m = 0; m < 16; m++) {
            float4 kd = *(const float4*)(kb + m * 64 + 4 * i);
            ulonglong2 va = *(const ulonglong2*)(vb + m * 64 + 8 * j);
            ulonglong2 vc = *(const ulonglong2*)(vb + m * 64 + 8 * j + 4);
            ull p;
            p = packf2(kd.x, kd.x);
            fma2(acc[0][0], p, va.x); fma2(acc[0][1], p, va.y);
            fma2(acc[0][2], p, vc.x); fma2(acc[0][3], p, vc.y);
            p = packf2(kd.y, kd.y);
            fma2(acc[1][0], p, va.x); fma2(acc[1][1], p, va.y);
            fma2(acc[1][2], p, vc.x); fma2(acc[1][3], p, vc.y);
            p = packf2(kd.z, kd.z);
            fma2(acc[2][0], p, va.x); fma2(acc[2][1], p, va.y);
            fma2(acc[2][2], p, vc.x); fma2(acc[2][3], p, vc.y);
            p = packf2(kd.w, kd.w);
            fma2(acc[3][0], p, va.x); fma2(acc[3][1], p, va.y);
            fma2(acc[3][2], p, vc.x); fma2(acc[3][3], p, vc.y);
        }
    }

    // store this block's partial kv tile (disjoint per thread — plain stores)
    float* dst = g_kvp + (size_t)(blockIdx.x * NBH + bh) * DD * DD;
#pragma unroll
    for (int a = 0; a < 4; a++) {
        float2 u0 = unpackf2(acc[a][0]);
        float2 u1 = unpackf2(acc[a][1]);
        float2 u2 = unpackf2(acc[a][2]);
        float2 u3 = unpackf2(acc[a][3]);
        float* row = dst + (4 * i + a) * 64 + 8 * j;
        *(float4*)(row)     = make_float4(u0.x, u0.y, u1.x, u1.y);
        *(float4*)(row + 4) = make_float4(u2.x, u2.y, u3.x, u3.y);
    }

    // ksum reduce: lanes l and l^16 hold the same c4 column group
    ks4.x += __shfl_xor_sync(0xffffffffu, ks4.x, 16);
    ks4.y += __shfl_xor_sync(0xffffffffu, ks4.y, 16);
    ks4.z += __shfl_xor_sync(0xffffffffu, ks4.z, 16);
    ks4.w += __shfl_xor_sync(0xffffffffu, ks4.w, 16);
    const int lane = tid & 31, w = tid >> 5;
    __syncthreads();     // done with ksh/vsh reads
    if (lane < 16)
        *(float4*)(ksbuf + (w * 16 + lane) * 4) = ks4;
    __syncthreads();
    if (tid < 64) {
        const int c4 = tid & 15, comp = tid >> 4;
        float s = 0.f;
#pragma unroll
        for (int ww = 0; ww < 4; ww++)
            s += ksbuf[(ww * 16 + c4) * 4 + comp];
        atomicAdd(&g_ksum[bh * DD + 4 * c4 + comp], s);
    }
}

// ---------- Pass 2 ---------- (R11 winner, verbatim)
// grid (32, 64), 128 threads, 128 tokens/block, thread tile 8t x 8f.
__global__ void __launch_bounds__(128)
pass2_kernel(const float* __restrict__ qq, float* __restrict__ out) {
    __shared__ float qsh[64 * 128];   // [d][t]
    __shared__ float kvsh[64 * 64];   // [d][f]
    __shared__ float kss[64];
    __shared__ float zsh[128];

    const int bh  = blockIdx.y;
    const int t0  = blockIdx.x * 128;
    const int tid = threadIdx.x;

    const float4* kvg = (const float4*)(g_kv + bh * DD * DD);
#pragma unroll
    for (int it = 0; it < 8; it++)
        ((float4*)kvsh)[it * 128 + tid] = kvg[it * 128 + tid];
    if (tid < 16)
        ((float4*)kss)[tid] = ((const float4*)(g_ksum + bh * DD))[tid];

    const float4* qg = (const float4*)(qq + (size_t)bh * SS * DD + (size_t)t0 * DD);
    float4 qr[16];
#pragma unroll
    for (int c = 0; c < 16; c++) {
        float4 x = qg[tid * 16 + c];
        x.x = fmap(x.x); x.y = fmap(x.y); x.z = fmap(x.z); x.w = fmap(x.w);
        qr[c] = x;
    }
    __syncthreads();

    float z = EPS;
#pragma unroll
    for (int c = 0; c < 16; c++) {
        z += qr[c].x * kss[4 * c] + qr[c].y * kss[4 * c + 1]
           + qr[c].z * kss[4 * c + 2] + qr[c].w * kss[4 * c + 3];
    }
    zsh[tid] = 1.0f / z;

#pragma unroll
    for (int c = 0; c < 16; c++) {
        qsh[(4 * c + 0) * 128 + tid] = qr[c].x;
        qsh[(4 * c + 1) * 128 + tid] = qr[c].y;
        qsh[(4 * c + 2) * 128 + tid] = qr[c].z;
        qsh[(4 * c + 3) * 128 + tid] = qr[c].w;
    }
    __syncthreads();

    const int ty = tid >> 3;   // 0..15
    const int tx = tid & 7;    // 0..7

    ull acc[8][4];
#pragma unroll
    for (int r = 0; r < 8; r++)
#pragma unroll
        for (int p = 0; p < 4; p++) acc[r][p] = 0ull;

#pragma unroll 4
    for (int d = 0; d < 64; d++) {
        float4 qa = *(const float4*)(qsh + d * 128 + 4 * ty);
        float4 qb = *(const float4*)(qsh + d * 128 + 64 + 4 * ty);
        ulonglong2 va = *(const ulonglong2*)(kvsh + d * 64 + 4 * tx);
        ulonglong2 vb = *(const ulonglong2*)(kvsh + d * 64 + 32 + 4 * tx);
        float qs[8] = {qa.x, qa.y, qa.z, qa.w, qb.x, qb.y, qb.z, qb.w};
#pragma unroll
        for (int r = 0; r < 8; r++) {
            ull qp = packf2(qs[r], qs[r]);
            fma2(acc[r][0], qp, va.x);
            fma2(acc[r][1], qp, va.y);
            fma2(acc[r][2], qp, vb.x);
            fma2(acc[r][3], qp, vb.y);
        }
    }

#pragma unroll
    for (int r = 0; r < 8; r++) {
        const int t = (r < 4) ? (4 * ty + r) : (64 + 4 * ty + r - 4);
        const float invz = zsh[t];
        float* og = out + (size_t)bh * SS * DD + (size_t)(t0 + t) * DD;
        float2 a0 = unpackf2(acc[r][0]);
        float2 a1 = unpackf2(acc[r][1]);
        float2 a2 = unpackf2(acc[r][2]);
        float2 a3 = unpackf2(acc[r][3]);
        float4 o0 = make_float4(a0.x * invz, a0.y * invz, a1.x * invz, a1.y * invz);
        float4 o1 = make_float4(a2.x * invz, a2.y * invz, a3.x * invz, a3.y * invz);
        *(float4*)(og + 4 * tx)      = o0;
        *(float4*)(og + 32 + 4 * tx) = o1;
    }
}

extern "C" void kernel_launch(void* const* d_in, const int* in_sizes, int n_in,
                              void* d_out, int out_size) {
    const float* q = (const float*)d_in[0];
    const float* k = (const float*)d_in[1];
    const float* v = (const float*)d_in[2];
    const void*  m = d_in[3];
    float* out = (float*)d_out;

    zero_kernel<<<16, 256>>>();
    detect_kernel<<<16, 256>>>((const unsigned int*)m);
    pass1_kernel<<<dim3(NCHUNK, NBH), 128>>>(k, v, m);
    reduce_kernel<<<512, 128>>>();
    pass2_kernel<<<dim3(SS / 128, NBH), 128>>>(q, out);
}

// round 15
// speedup vs baseline: 1.1063x; 1.0022x over previous
#include <cuda_runtime.h>

#define BB 4
#define HH 16
#define SS 4096
#define DD 64
#define NBH (BB*HH)
#define NCHUNK 16
#define EPS 1e-6f

__device__ float g_kv[NBH * DD * DD];             // [bh][d][f] (final)
__device__ float g_kvp[NCHUNK * NBH * DD * DD];   // per-chunk partials (16MB)
__device__ float g_ksum[NBH * DD];                // [bh][d]
__device__ int   g_mask_fmt;                      // 0 = 4-byte elems, 1 = 1-byte

typedef unsigned long long ull;

// ---------- helpers ----------
__device__ __forceinline__ float fmap(float x) {
    return x > 0.0f ? x + 1.0f : __expf(x);
}

__device__ __forceinline__ void fma2(ull &acc, ull a, ull b) {
    asm("fma.rn.f32x2 %0, %1, %2, %0;" : "+l"(acc) : "l"(a), "l"(b));
}

__device__ __forceinline__ ull packf2(float x, float y) {
    ull r;
    asm("mov.b64 %0, {%1, %2};" : "=l"(r) : "f"(x), "f"(y));
    return r;
}

__device__ __forceinline__ float2 unpackf2(ull v) {
    float2 r;
    asm("mov.b64 {%0, %1}, %2;" : "=f"(r.x), "=f"(r.y) : "l"(v));
    return r;
}

__device__ __forceinline__ float get_valid(const void* mask, int fmt, int idx) {
    if (fmt) return ((const unsigned char*)mask)[idx] == 0 ? 1.0f : 0.0f;
    return ((const unsigned int*)mask)[idx] == 0u ? 1.0f : 0.0f;
}

// ---------- small kernels ----------
__global__ void zero_kernel() {
    int idx = blockIdx.x * blockDim.x + threadIdx.x;
    if (idx < NBH * DD) g_ksum[idx] = 0.0f;
    if (idx == 0)       g_mask_fmt = 0;
}

__global__ void detect_kernel(const unsigned int* __restrict__ mask) {
    int idx = blockIdx.x * blockDim.x + threadIdx.x;  // 4096 threads
    unsigned int w = mask[idx];
    if (w != 0u && w != 1u && w != 0x3F800000u) atomicOr(&g_mask_fmt, 1);
}

// Sum the NCHUNK partial kv matrices. grid 512 x 128 threads, 1 float4/thread.
__global__ void __launch_bounds__(128)
reduce_kernel() {
    const int gidx = blockIdx.x * 128 + threadIdx.x;   // 0..65535
    const int bh  = gidx >> 10;
    const int pos = gidx & 1023;
    const float4* src = (const float4*)g_kvp;
    float4 s = src[(size_t)bh * 1024 + pos];
#pragma unroll
    for (int c = 1; c < NCHUNK; c++) {
        float4 t = src[(size_t)(c * NBH + bh) * 1024 + pos];
        s.x += t.x; s.y += t.y; s.z += t.z; s.w += t.w;
    }
    ((float4*)(g_kv + bh * DD * DD))[pos] = s;
}

// ---------- Pass 1 ----------
// grid (NCHUNK, 64) = 1024 blocks, 128 threads. Thread (i=tid&15, j=tid>>4)
// owns the DISJOINT tile d=4i..4i+3 x f=8j..8j+7. 256 tokens/block,
// 16-token double-buffered stages, loader-side ksum.
__global__ void __launch_bounds__(128)
pass1_kernel(const float* __restrict__ kk, const float* __restrict__ vv,
             const void* __restrict__ mask) {
    __shared__ float ksh[2][1024];        // 16 tokens x 64
    __shared__ float vsh[2][1024];
    __shared__ float ksbuf[4 * 16 * 4];   // per-warp ksum partials

    const int bh  = blockIdx.y;
    const int s0  = blockIdx.x * 256;
    const int tid = threadIdx.x;
    const int i   = tid & 15;        // d group: d = 4i..4i+3
    const int j   = tid >> 4;        // f group: f = 8j..8j+7
    const int fmt = g_mask_fmt;
    const int b   = bh >> 4;

    const float4* kg = (const float4*)(kk + (size_t)bh * SS * DD);
    const float4* vg = (const float4*)(vv + (size_t)bh * SS * DD);

    ull acc[4][4];
#pragma unroll
    for (int a = 0; a < 4; a++)
#pragma unroll
        for (int p = 0; p < 4; p++) acc[a][p] = 0ull;
    float4 ks4 = make_float4(0.f, 0.f, 0.f, 0.f);

    float4 kr[2], vr[2];

    // prefetch stage 0 (16 tokens = 256 float4, 2 per thread)
#pragma unroll
    for (int it = 0; it < 2; it++) {
        int vi = it * 128 + tid;
        int sl = vi >> 4, c4 = vi & 15;
        float valid = get_valid(mask, fmt, b * SS + s0 + sl);
        float4 k4 = kg[(size_t)(s0 + sl) * 16 + c4];
        vr[it] = vg[(size_t)(s0 + sl) * 16 + c4];
        k4.x = fmap(k4.x) * valid;
        k4.y = fmap(k4.y) * valid;
        k4.z = fmap(k4.z) * valid;
        k4.w = fmap(k4.w) * valid;
        kr[it] = k4;
        ks4.x += k4.x; ks4.y += k4.y; ks4.z += k4.z; ks4.w += k4.w;
    }

    for (int st = 0; st < 16; st++) {
        const int bufi = st & 1;
#pragma unroll
        for (int it = 0; it < 2; it++) {
            ((float4*)ksh[bufi])[it * 128 + tid] = kr[it];
            ((float4*)vsh[bufi])[it * 128 + tid] = vr[it];
        }
        __syncthreads();

        // prefetch next stage (overlaps with compute below)
        if (st < 15) {
            const int sbase = s0 + (st + 1) * 16;
#pragma unroll
            for (int it = 0; it < 2; it++) {
                int vi = it * 128 + tid;
                int sl = vi >> 4, c4 = vi & 15;
                float valid = get_valid(mask, fmt, b * SS + sbase + sl);
                float4 k4 = kg[(size_t)(sbase + sl) * 16 + c4];
                vr[it] = vg[(size_t)(sbase + sl) * 16 + c4];
                k4.x = fmap(k4.x) * valid;
                k4.y = fmap(k4.y) * valid;
                k4.z = fmap(k4.z) * valid;
                k4.w = fmap(k4.w) * valid;
                kr[it] = k4;
                ks4.x += k4.x; ks4.y += k4.y; ks4.z += k4.z; ks4.w += k4.w;
            }
        }

        // compute 16 tokens: 3 LDS.128 + 4 packs + 16 FMA2 per token
        const float* kb = ksh[bufi];
        const float* vb = vsh[bufi];
#pragma unroll 8
        for (int m = 0; m < 16; m++) {
            float4 kd = *(const float4*)(kb + m * 64 + 4 * i);
            ulonglong2 va = *(const ulonglong2*)(vb + m * 64 + 8 * j);
            ulonglong2 vc = *(const ulonglong2*)(vb + m * 64 + 8 * j + 4);
            ull p;
            p = packf2(kd.x, kd.x);
            fma2(acc[0][0], p, va.x); fma2(acc[0][1], p, va.y);
            fma2(acc[0][2], p, vc.x); fma2(acc[0][3], p, vc.y);
            p = packf2(kd.y, kd.y);
            fma2(acc[1][0], p, va.x); fma2(acc[1][1], p, va.y);
            fma2(acc[1][2], p, vc.x); fma2(acc[1][3], p, vc.y);
            p = packf2(kd.z, kd.z);
            fma2(acc[2][0], p, va.x); fma2(acc[2][1], p, va.y);
            fma2(acc[2][2], p, vc.x); fma2(acc[2][3], p, vc.y);
            p = packf2(kd.w, kd.w);
            fma2(acc[3][0], p, va.x); fma2(acc[3][1], p, va.y);
            fma2(acc[3][2], p, vc.x); fma2(acc[3][3], p, vc.y);
        }
    }

    // store this block's partial kv tile (disjoint per thread — plain stores)
    float* dst = g_kvp + (size_t)(blockIdx.x * NBH + bh) * DD * DD;
#pragma unroll
    for (int a = 0; a < 4; a++) {
        float2 u0 = unpackf2(acc[a][0]);
        float2 u1 = unpackf2(acc[a][1]);
        float2 u2 = unpackf2(acc[a][2]);
        float2 u3 = unpackf2(acc[a][3]);
        float* row = dst + (4 * i + a) * 64 + 8 * j;
        *(float4*)(row)     = make_float4(u0.x, u0.y, u1.x, u1.y);
        *(float4*)(row + 4) = make_float4(u2.x, u2.y, u3.x, u3.y);
    }

    // ksum reduce: lanes l and l^16 hold the same c4 column group
    ks4.x += __shfl_xor_sync(0xffffffffu, ks4.x, 16);
    ks4.y += __shfl_xor_sync(0xffffffffu, ks4.y, 16);
    ks4.z += __shfl_xor_sync(0xffffffffu, ks4.z, 16);
    ks4.w += __shfl_xor_sync(0xffffffffu, ks4.w, 16);
    const int lane = tid & 31, w = tid >> 5;
    __syncthreads();     // done with ksh/vsh reads
    if (lane < 16)
        *(float4*)(ksbuf + (w * 16 + lane) * 4) = ks4;
    __syncthreads();
    if (tid < 64) {
        const int c4 = tid & 15, comp = tid >> 4;
        float s = 0.f;
#pragma unroll
        for (int ww = 0; ww < 4; ww++)
            s += ksbuf[(ww * 16 + c4) * 4 + comp];
        atomicAdd(&g_ksum[bh * DD + 4 * c4 + comp], s);
    }
}

// ---------- Pass 2 ---------- (R11 winner, verbatim)
// grid (32, 64), 128 threads, 128 tokens/block, thread tile 8t x 8f.
__global__ void __launch_bounds__(128)
pass2_kernel(const float* __restrict__ qq, float* __restrict__ out) {
    __shared__ float qsh[64 * 128];   // [d][t]
    __shared__ float kvsh[64 * 64];   // [d][f]
    __shared__ float kss[64];
    __shared__ float zsh[128];

    const int bh  = blockIdx.y;
    const int t0  = blockIdx.x * 128;
    const int tid = threadIdx.x;

    const float4* kvg = (const float4*)(g_kv + bh * DD * DD);
#pragma unroll
    for (int it = 0; it < 8; it++)
        ((float4*)kvsh)[it * 128 + tid] = kvg[it * 128 + tid];
    if (tid < 16)
        ((float4*)kss)[tid] = ((const float4*)(g_ksum + bh * DD))[tid];

    const float4* qg = (const float4*)(qq + (size_t)bh * SS * DD + (size_t)t0 * DD);
    float4 qr[16];
#pragma unroll
    for (int c = 0; c < 16; c++) {
        float4 x = qg[tid * 16 + c];
        x.x = fmap(x.x); x.y = fmap(x.y); x.z = fmap(x.z); x.w = fmap(x.w);
        qr[c] = x;
    }
    __syncthreads();

    float z = EPS;
#pragma unroll
    for (int c = 0; c < 16; c++) {
        z += qr[c].x * kss[4 * c] + qr[c].y * kss[4 * c + 1]
           + qr[c].z * kss[4 * c + 2] + qr[c].w * kss[4 * c + 3];
    }
    zsh[tid] = 1.0f / z;

#pragma unroll
    for (int c = 0; c < 16; c++) {
        qsh[(4 * c + 0) * 128 + tid] = qr[c].x;
        qsh[(4 * c + 1) * 128 + tid] = qr[c].y;
        qsh[(4 * c + 2) * 128 + tid] = qr[c].z;
        qsh[(4 * c + 3) * 128 + tid] = qr[c].w;
    }
    __syncthreads();

    const int ty = tid >> 3;   // 0..15
    const int tx = tid & 7;    // 0..7

    ull acc[8][4];
#pragma unroll
    for (int r = 0; r < 8; r++)
#pragma unroll
        for (int p = 0; p < 4; p++) acc[r][p] = 0ull;

#pragma unroll 4
    for (int d = 0; d < 64; d++) {
        float4 qa = *(const float4*)(qsh + d * 128 + 4 * ty);
        float4 qb = *(const float4*)(qsh + d * 128 + 64 + 4 * ty);
        ulonglong2 va = *(const ulonglong2*)(kvsh + d * 64 + 4 * tx);
        ulonglong2 vb = *(const ulonglong2*)(kvsh + d * 64 + 32 + 4 * tx);
        float qs[8] = {qa.x, qa.y, qa.z, qa.w, qb.x, qb.y, qb.z, qb.w};
#pragma unroll
        for (int r = 0; r < 8; r++) {
            ull qp = packf2(qs[r], qs[r]);
            fma2(acc[r][0], qp, va.x);
            fma2(acc[r][1], qp, va.y);
            fma2(acc[r][2], qp, vb.x);
            fma2(acc[r][3], qp, vb.y);
        }
    }

#pragma unroll
    for (int r = 0; r < 8; r++) {
        const int t = (r < 4) ? (4 * ty + r) : (64 + 4 * ty + r - 4);
        const float invz = zsh[t];
        float* og = out + (size_t)bh * SS * DD + (size_t)(t0 + t) * DD;
        float2 a0 = unpackf2(acc[r][0]);
        float2 a1 = unpackf2(acc[r][1]);
        float2 a2 = unpackf2(acc[r][2]);
        float2 a3 = unpackf2(acc[r][3]);
        float4 o0 = make_float4(a0.x * invz, a0.y * invz, a1.x * invz, a1.y * invz);
        float4 o1 = make_float4(a2.x * invz, a2.y * invz, a3.x * invz, a3.y * invz);
        *(float4*)(og + 4 * tx)      = o0;
        *(float4*)(og + 32 + 4 * tx) = o1;
    }
}

extern "C" void kernel_launch(void* const* d_in, const int* in_sizes, int n_in,
                              void* d_out, int out_size) {
    const float* q = (const float*)d_in[0];
    const float* k = (const float*)d_in[1];
    const float* v = (const float*)d_in[2];
    const void*  m = d_in[3];
    float* out = (float*)d_out;

    zero_kernel<<<16, 256>>>();
    detect_kernel<<<16, 256>>>((const unsigned int*)m);
    pass1_kernel<<<dim3(NCHUNK, NBH), 128>>>(k, v, m);
    reduce_kernel<<<512, 128>>>();
    pass2_kernel<<<dim3(SS / 128, NBH), 128>>>(q, out);
}